// round 2
// baseline (speedup 1.0000x reference)
#include <cuda_runtime.h>
#include <math.h>

// Problem constants
#define T_LEN  2048
#define B_SZ   32
#define IN_SZ  256
#define H_SZ   512
#define OUT_SZ 256
#define DT_C   0.1f

// Decomposition: 32 row-groups x 4 batch-groups (pods) = 128 CTAs, 1 per SM.
#define RGROUPS 32
#define BGROUPS 4
#define NCTA    128
#define RPC     16   // hidden rows per CTA (per layer)
#define OPC     8    // output rows per CTA
#define BPC     8    // batches per CTA (per pod)
#define NTHR    256

// SMEM pitches (floats). All are %4==0 (float4 aligned) and ==4 (mod 32)
// so the 8 distinct row lanes in a warp hit distinct 4-bank groups -> conflict-free LDS.128.
#define P0 772    // layer0 weight rows: 768 cols used
#define P1 1028   // layer1 weight rows: 1024 cols used
#define PO 516    // out weight rows: 512 cols used
#define PA 1028   // activation rows: up to 1024 cols used
#define PX 256    // x_t slice (kept for the residual add)

#define SMEM_FLOATS (RPC*P0 + RPC*P1 + OPC*PO + BPC*PA + BPC*PX + 1024 + 4*RPC + OPC)
#define SMEM_BYTES  (SMEM_FLOATS * 4)

// Persistent state (double-buffered) + pod barrier counters (128B apart).
__device__ float    g_h0[2][B_SZ][H_SZ];
__device__ float    g_h1[2][B_SZ][H_SZ];
__device__ unsigned g_cnt[BGROUPS * 32];

__global__ void init_state_kernel() {
    int i = blockIdx.x * blockDim.x + threadIdx.x;
    const int n = 2 * B_SZ * H_SZ;
    if (i < n) {
        ((float*)g_h0)[i] = 0.0f;
        ((float*)g_h1)[i] = 0.0f;
    }
    if (i < BGROUPS * 32) g_cnt[i] = 0u;
}

// Monotonic-counter pod barrier (32 CTAs). Release: syncthreads orders all CTA
// writes before thread0's gpu fence + arrive. Acquire: volatile L2 spin + fence.
__device__ __forceinline__ void pod_barrier(unsigned* cnt, unsigned target) {
    __syncthreads();
    if (threadIdx.x == 0) {
        __threadfence();
        atomicAdd(cnt, 1u);
        while (*((volatile unsigned*)cnt) < target) { }
        __threadfence();
    }
    __syncthreads();
}

// 2 rows x 2 batches register micro-tile over a K-slice.
// acc.x=(rA,bA) acc.y=(rA,bB) acc.z=(rB,bA) acc.w=(rB,bB)
template<int ITERS, int STRIDE>
__device__ __forceinline__ float4 gemm_tile(const float* wA, const float* wB,
                                            const float* aA, const float* aB) {
    float4 acc = make_float4(0.f, 0.f, 0.f, 0.f);
#pragma unroll
    for (int i = 0; i < ITERS; i++) {
        float4 w0 = *(const float4*)(wA + STRIDE * i);
        float4 w1 = *(const float4*)(wB + STRIDE * i);
        float4 a0 = *(const float4*)(aA + STRIDE * i);
        float4 a1 = *(const float4*)(aB + STRIDE * i);
        acc.x = fmaf(w0.w,a0.w, fmaf(w0.z,a0.z, fmaf(w0.y,a0.y, fmaf(w0.x,a0.x, acc.x))));
        acc.y = fmaf(w0.w,a1.w, fmaf(w0.z,a1.z, fmaf(w0.y,a1.y, fmaf(w0.x,a1.x, acc.y))));
        acc.z = fmaf(w1.w,a0.w, fmaf(w1.z,a0.z, fmaf(w1.y,a0.y, fmaf(w1.x,a0.x, acc.z))));
        acc.w = fmaf(w1.w,a1.w, fmaf(w1.z,a1.z, fmaf(w1.y,a1.y, fmaf(w1.x,a1.x, acc.w))));
    }
    return acc;
}

__global__ void __launch_bounds__(NTHR, 1)
rnn_persistent(const float* __restrict__ x,
               const float* __restrict__ Win0, const float* __restrict__ bin0,
               const float* __restrict__ Wrec0, const float* __restrict__ tau0,
               const float* __restrict__ Win1, const float* __restrict__ bin1,
               const float* __restrict__ Wrec1, const float* __restrict__ tau1,
               const float* __restrict__ Wout, const float* __restrict__ bout,
               float* __restrict__ out)
{
    extern __shared__ float sm[];
    float* sW0  = sm;                    // [16][P0]   cols 0:256=Win0, 256:768=Wrec0
    float* sW1  = sW0  + RPC * P0;       // [16][P1]   cols 0:512=Win1, 512:1024=Wrec1
    float* sWo  = sW1  + RPC * P1;       // [8][PO]
    float* sAct = sWo  + OPC * PO;       // [8][PA]    phase-dependent activations
    float* sX   = sAct + BPC * PA;       // [8][256]   x_t slice (residual)
    float* sRed = sX   + BPC * PX;       // [1024]     k-slice partials
    float* sB0  = sRed + 1024;
    float* sIT0 = sB0  + RPC;
    float* sB1  = sIT0 + RPC;
    float* sIT1 = sB1  + RPC;
    float* sBo  = sIT1 + RPC;

    const int tid = threadIdx.x;
    const int rg  = blockIdx.x & (RGROUPS - 1);
    const int bg  = blockIdx.x >> 5;
    const int b0  = bg * BPC;
    const int r0  = rg * RPC;
    const int o0  = rg * OPC;
    unsigned* cnt = &g_cnt[bg * 32];

    // ---- Load weight slices into SMEM (once) ----
    for (int idx = tid; idx < RPC * 768; idx += NTHR) {
        int r = idx / 768, c = idx % 768;
        float v = (c < IN_SZ) ? Win0[(r0 + r) * IN_SZ + c]
                              : Wrec0[(r0 + r) * H_SZ + (c - IN_SZ)];
        sW0[r * P0 + c] = v;
    }
    for (int idx = tid; idx < RPC * 1024; idx += NTHR) {
        int r = idx >> 10, c = idx & 1023;
        float v = (c < H_SZ) ? Win1[(r0 + r) * H_SZ + c]
                             : Wrec1[(r0 + r) * H_SZ + (c - H_SZ)];
        sW1[r * P1 + c] = v;
    }
    for (int idx = tid; idx < OPC * H_SZ; idx += NTHR) {
        int r = idx >> 9, c = idx & 511;
        sWo[r * PO + c] = Wout[(o0 + r) * H_SZ + c];
    }
    if (tid < RPC) {
        sB0[tid] = bin0[r0 + tid];
        float tc = fminf(fmaxf(tau0[r0 + tid], 0.1f), 10.f);
        sIT0[tid] = DT_C / tc;
        sB1[tid] = bin1[r0 + tid];
        tc = fminf(fmaxf(tau1[r0 + tid], 0.1f), 10.f);
        sIT1[tid] = DT_C / tc;
    }
    if (tid < OPC) sBo[tid] = bout[o0 + tid];
    __syncthreads();

    // Thread tiling decode
    // Phases A/B: warp == one k-slice of 32 tiles (8 r-tiles x 4 b-tiles)
    const int ksAB  = tid >> 5;
    const int tAB   = tid & 31;
    const int btAB  = tAB >> 3;
    const int rtAB  = tAB & 7;
    // Phase C: 16 k-slices x 16 tiles (4 o-tiles x 4 b-tiles)
    const int ksC = tid >> 4;
    const int tC  = tid & 15;
    const int btC = tC >> 2;
    const int otC = tC & 3;

    unsigned bar_target = 0;

    for (int t = 0; t < T_LEN; t++) {
        const int pr = t & 1;
        const int pw = pr ^ 1;

        // ================= Phase A: layer 0 =================
        // stage x_t -> sX and sAct[:,0:256]; h0_old -> sAct[:,256:768]
#pragma unroll
        for (int idx = tid; idx < BPC * 64; idx += NTHR) {
            int bb = idx >> 6, c = (idx & 63) << 2;
            float4 v = *(const float4*)&x[((size_t)(b0 + bb) * T_LEN + t) * IN_SZ + c];
            *(float4*)&sX[bb * PX + c]   = v;
            *(float4*)&sAct[bb * PA + c] = v;
        }
#pragma unroll
        for (int idx = tid; idx < BPC * 128; idx += NTHR) {
            int bb = idx >> 7, c = (idx & 127) << 2;
            float4 v = *(const float4*)&g_h0[pr][b0 + bb][c];
            *(float4*)&sAct[bb * PA + 256 + c] = v;
        }
        __syncthreads();
        {
            const int kb = ksAB * 96;  // 768/8
            float4 acc = gemm_tile<24, 4>(&sW0[rtAB * P0 + kb], &sW0[(rtAB + 8) * P0 + kb],
                                          &sAct[btAB * PA + kb], &sAct[(btAB + 4) * PA + kb]);
            sRed[((btAB)     * 16 + rtAB    ) * 8 + ksAB] = acc.x;
            sRed[((btAB + 4) * 16 + rtAB    ) * 8 + ksAB] = acc.y;
            sRed[((btAB)     * 16 + rtAB + 8) * 8 + ksAB] = acc.z;
            sRed[((btAB + 4) * 16 + rtAB + 8) * 8 + ksAB] = acc.w;
        }
        __syncthreads();
        if (tid < 128) {
            int bb = tid >> 4, r = tid & 15;
            const float4* p = (const float4*)&sRed[(bb * 16 + r) * 8];
            float4 s0 = p[0], s1 = p[1];
            float sum = s0.x + s0.y + s0.z + s0.w + s1.x + s1.y + s1.z + s1.w + sB0[r];
            float tgt  = tanhf(sum);
            float hold = sAct[bb * PA + 256 + r0 + r];
            float hn   = hold + (tgt - hold) * sIT0[r];
            g_h0[pw][b0 + bb][r0 + r] = hn;
        }
        bar_target += 32;
        pod_barrier(cnt, bar_target);

        // ================= Phase B: layer 1 =================
        // stage h0_new -> sAct[:,0:512]; h1_old -> sAct[:,512:1024]
#pragma unroll
        for (int idx = tid; idx < BPC * 128; idx += NTHR) {
            int bb = idx >> 7, c = (idx & 127) << 2;
            float4 v = *(const float4*)&g_h0[pw][b0 + bb][c];
            *(float4*)&sAct[bb * PA + c] = v;
        }
#pragma unroll
        for (int idx = tid; idx < BPC * 128; idx += NTHR) {
            int bb = idx >> 7, c = (idx & 127) << 2;
            float4 v = *(const float4*)&g_h1[pr][b0 + bb][c];
            *(float4*)&sAct[bb * PA + 512 + c] = v;
        }
        __syncthreads();
        {
            const int kb = ksAB * 128;  // 1024/8
            float4 acc = gemm_tile<32, 4>(&sW1[rtAB * P1 + kb], &sW1[(rtAB + 8) * P1 + kb],
                                          &sAct[btAB * PA + kb], &sAct[(btAB + 4) * PA + kb]);
            sRed[((btAB)     * 16 + rtAB    ) * 8 + ksAB] = acc.x;
            sRed[((btAB + 4) * 16 + rtAB    ) * 8 + ksAB] = acc.y;
            sRed[((btAB)     * 16 + rtAB + 8) * 8 + ksAB] = acc.z;
            sRed[((btAB + 4) * 16 + rtAB + 8) * 8 + ksAB] = acc.w;
        }
        __syncthreads();
        if (tid < 128) {
            int bb = tid >> 4, r = tid & 15;
            const float4* p = (const float4*)&sRed[(bb * 16 + r) * 8];
            float4 s0 = p[0], s1 = p[1];
            float sum = s0.x + s0.y + s0.z + s0.w + s1.x + s1.y + s1.z + s1.w + sB1[r];
            float tgt  = tanhf(sum);
            float hold = sAct[bb * PA + 512 + r0 + r];
            float hn   = hold + (tgt - hold) * sIT1[r];
            g_h1[pw][b0 + bb][r0 + r] = hn;
        }
        bar_target += 32;
        pod_barrier(cnt, bar_target);

        // ================= Phase C: output projection + residual =================
#pragma unroll
        for (int idx = tid; idx < BPC * 128; idx += NTHR) {
            int bb = idx >> 7, c = (idx & 127) << 2;
            float4 v = *(const float4*)&g_h1[pw][b0 + bb][c];
            *(float4*)&sAct[bb * PA + c] = v;
        }
        __syncthreads();
        {
            // k = ksC*4 + 64*j  (interleaved so the two k-slices in a warp hit
            // adjacent non-conflicting bank groups)
            const int kb = ksC * 4;
            float4 acc = gemm_tile<8, 64>(&sWo[otC * PO + kb], &sWo[(otC + 4) * PO + kb],
                                          &sAct[btC * PA + kb], &sAct[(btC + 4) * PA + kb]);
            sRed[((btC)     * 8 + otC    ) * 16 + ksC] = acc.x;
            sRed[((btC + 4) * 8 + otC    ) * 16 + ksC] = acc.y;
            sRed[((btC)     * 8 + otC + 4) * 16 + ksC] = acc.z;
            sRed[((btC + 4) * 8 + otC + 4) * 16 + ksC] = acc.w;
        }
        __syncthreads();
        if (tid < 64) {
            int bb = tid >> 3, o = tid & 7;
            const float4* p = (const float4*)&sRed[(bb * 8 + o) * 16];
            float4 s0 = p[0], s1 = p[1], s2 = p[2], s3 = p[3];
            float sum = s0.x+s0.y+s0.z+s0.w + s1.x+s1.y+s1.z+s1.w
                      + s2.x+s2.y+s2.z+s2.w + s3.x+s3.y+s3.z+s3.w;
            float val = sum + sBo[o] + sX[bb * PX + o0 + o];
            out[((size_t)(b0 + bb) * T_LEN + t) * OUT_SZ + o0 + o] = val;
        }
        __syncthreads();  // protect sX/sAct before next step's staging
    }
}

extern "C" void kernel_launch(void* const* d_in, const int* in_sizes, int n_in,
                              void* d_out, int out_size) {
    const float* x     = (const float*)d_in[0];
    const float* Win0  = (const float*)d_in[1];
    const float* bin0  = (const float*)d_in[2];
    const float* Wrec0 = (const float*)d_in[3];
    const float* tau0  = (const float*)d_in[4];
    const float* Win1  = (const float*)d_in[5];
    const float* bin1  = (const float*)d_in[6];
    const float* Wrec1 = (const float*)d_in[7];
    const float* tau1  = (const float*)d_in[8];
    const float* Wout  = (const float*)d_in[9];
    const float* bout  = (const float*)d_in[10];
    float* outp        = (float*)d_out;

    cudaFuncSetAttribute(rnn_persistent,
                         cudaFuncAttributeMaxDynamicSharedMemorySize, SMEM_BYTES);

    init_state_kernel<<<128, 256>>>();
    rnn_persistent<<<NCTA, NTHR, SMEM_BYTES>>>(x, Win0, bin0, Wrec0, tau0,
                                               Win1, bin1, Wrec1, tau1,
                                               Wout, bout, outp);
}

// round 4
// speedup vs baseline: 1.2479x; 1.2479x over previous
#include <cuda_runtime.h>
#include <math.h>
#include <stdint.h>

#define T_LEN  2048
#define B_SZ   32
#define IN_SZ  256
#define H_SZ   512
#define OUT_SZ 256
#define DT_C   0.1f

#define RGROUPS 32
#define BGROUPS 4
#define NCTA    128
#define RPC     16   // hidden rows per CTA
#define OPC     8    // output rows per CTA
#define BPC     8    // batches per CTA
#define NTHR    256

// Pitches (floats), all %4==0 and ==4 (mod 32)
#define P0  772    // W0 rows (768 used: 256 Win0 | 512 Wrec0)
#define P1  1028   // W1 rows (1024 used: 512 Win1 | 512 Wrec1)
#define POW 516    // Wout rows (512 used)
#define PAA 772    // A-activations (256 x | 512 h0old)
#define PBB 1028   // B-activations (512 h0new | 512 h1old)
#define PCC 516    // C-activations (512 h1new)

#define SMEM_FLOATS (RPC*P0 + RPC*P1 + OPC*POW + BPC*PAA + BPC*PBB + BPC*PCC + 4224 + 72)
#define SMEM_BYTES  (SMEM_FLOATS * 4)

__device__ float    g_h0[2][B_SZ][H_SZ];
__device__ float    g_h1[2][B_SZ][H_SZ];
__device__ unsigned g_cnt[BGROUPS * 32];

__global__ void init_state_kernel() {
    int i = blockIdx.x * blockDim.x + threadIdx.x;
    const int n = 2 * B_SZ * H_SZ;
    if (i < n) {
        ((float*)g_h0)[i] = 0.0f;
        ((float*)g_h1)[i] = 0.0f;
    }
    if (i < BGROUPS * 32) g_cnt[i] = 0u;
}

__device__ __forceinline__ void cpa16(uint32_t dst, const void* src) {
    asm volatile("cp.async.cg.shared.global [%0], [%1], 16;"
                 :: "r"(dst), "l"(src) : "memory");
}
#define CP_COMMIT() asm volatile("cp.async.commit_group;" ::: "memory")
#define CP_WAIT(n)  asm volatile("cp.async.wait_group %0;" :: "n"(n) : "memory")

// Stage one full h-vector set (8 batches x 512 floats) into smem at pitch PIT,
// column offset COFF. All 256 threads, 4 float4 each.
template<int PIT, int COFF>
__device__ __forceinline__ void stage_h(uint32_t ubase, const float* __restrict__ g,
                                        int b0, int bb, int c) {
#pragma unroll
    for (int q = 0; q < 4; q++) {
        cpa16(ubase + (bb * PIT + COFF + c + q * 128) * 4,
              &g[(size_t)(b0 + bb) * H_SZ + c + q * 128]);
    }
}

// 32-CTA pod barrier: monotonic counter in L2.
__device__ __forceinline__ void pod_bar(unsigned* cnt, unsigned target) {
    __syncthreads();
    if (threadIdx.x == 0) {
        __threadfence();
        atomicAdd(cnt, 1u);
        unsigned v;
        do {
            asm volatile("ld.acquire.gpu.global.u32 %0, [%1];"
                         : "=r"(v) : "l"(cnt) : "memory");
        } while (v < target);
    }
    __syncthreads();
}

// 4x4 register micro-tile over NIT k-chunks of 4 floats, step KSTEP floats.
template<int NIT, int KSTEP, int PW, int PAcc>
__device__ __forceinline__ void mm44(const float* __restrict__ sW, int rbase,
                                     const float* __restrict__ sAct, int bbase,
                                     int kbase, float acc[4][4]) {
#pragma unroll
    for (int it = 0; it < NIT; ++it) {
        const int k = kbase + it * KSTEP;
        float4 w0 = *(const float4*)(sW + (rbase + 0) * PW + k);
        float4 w1 = *(const float4*)(sW + (rbase + 1) * PW + k);
        float4 w2 = *(const float4*)(sW + (rbase + 2) * PW + k);
        float4 w3 = *(const float4*)(sW + (rbase + 3) * PW + k);
        float4 a0 = *(const float4*)(sAct + (bbase + 0) * PAcc + k);
        float4 a1 = *(const float4*)(sAct + (bbase + 1) * PAcc + k);
        float4 a2 = *(const float4*)(sAct + (bbase + 2) * PAcc + k);
        float4 a3 = *(const float4*)(sAct + (bbase + 3) * PAcc + k);
        const float4 W[4] = {w0, w1, w2, w3};
        const float4 A[4] = {a0, a1, a2, a3};
#pragma unroll
        for (int i = 0; i < 4; i++)
#pragma unroll
            for (int j = 0; j < 4; j++)
                acc[i][j] = fmaf(W[i].w, A[j].w,
                             fmaf(W[i].z, A[j].z,
                              fmaf(W[i].y, A[j].y,
                               fmaf(W[i].x, A[j].x, acc[i][j]))));
    }
}

__global__ void __launch_bounds__(NTHR, 1)
rnn_persistent(const float* __restrict__ x,
               const float* __restrict__ Win0, const float* __restrict__ bin0,
               const float* __restrict__ Wrec0, const float* __restrict__ tau0,
               const float* __restrict__ Win1, const float* __restrict__ bin1,
               const float* __restrict__ Wrec1, const float* __restrict__ tau1,
               const float* __restrict__ Wout, const float* __restrict__ bout,
               float* __restrict__ out)
{
    extern __shared__ float sm[];
    float* sW0  = sm;                   // [16][P0]
    float* sW1  = sW0 + RPC * P0;       // [16][P1]
    float* sWo  = sW1 + RPC * P1;       // [8][POW]
    float* sA   = sWo + OPC * POW;      // [8][PAA]  x | h0old
    float* sB   = sA  + BPC * PAA;      // [8][PBB]  h0new | h1old
    float* sC   = sB  + BPC * PBB;      // [8][PCC]  h1new
    float* sRed = sC  + BPC * PCC;      // 4224 floats scratch
    float* sBi0 = sRed + 4224;          // 16
    float* sIT0 = sBi0 + RPC;           // 16
    float* sBi1 = sIT0 + RPC;           // 16
    float* sIT1 = sBi1 + RPC;           // 16
    float* sBo  = sIT1 + RPC;           // 8

    const int tid = threadIdx.x;
    const int rg  = blockIdx.x & (RGROUPS - 1);
    const int bg  = blockIdx.x >> 5;
    const int b0  = bg * BPC;
    const int r0  = rg * RPC;
    const int o0  = rg * OPC;
    unsigned* cnt = &g_cnt[bg * 32];

    const uint32_t uA = (uint32_t)__cvta_generic_to_shared(sA);
    const uint32_t uB = (uint32_t)__cvta_generic_to_shared(sB);
    const uint32_t uC = (uint32_t)__cvta_generic_to_shared(sC);

    // staging decode: bb = batch, c = base float col (each thread: 4 float4
    // for h rows, 2 float4 for x rows)
    const int st_bb = tid >> 5;            // 0..7
    const int st_c  = (tid & 31) * 4;      // 0..124

    // ---- Prologue: kick off step-0 staging immediately ----
    cpa16(uA + (st_bb * PAA + st_c) * 4,
          &x[((size_t)(b0 + st_bb) * T_LEN + 0) * IN_SZ + st_c]);
    cpa16(uA + (st_bb * PAA + st_c + 128) * 4,
          &x[((size_t)(b0 + st_bb) * T_LEN + 0) * IN_SZ + st_c + 128]);
    stage_h<PAA, 256>(uA, &g_h0[0][0][0], b0, st_bb, st_c);
    CP_COMMIT();

    // ---- Weight slices into SMEM (once) ----
    for (int idx = tid; idx < RPC * 768; idx += NTHR) {
        int r = idx / 768, c = idx % 768;
        float v = (c < IN_SZ) ? Win0[(r0 + r) * IN_SZ + c]
                              : Wrec0[(r0 + r) * H_SZ + (c - IN_SZ)];
        sW0[r * P0 + c] = v;
    }
    for (int idx = tid; idx < RPC * 1024; idx += NTHR) {
        int r = idx >> 10, c = idx & 1023;
        float v = (c < H_SZ) ? Win1[(r0 + r) * H_SZ + c]
                             : Wrec1[(r0 + r) * H_SZ + (c - H_SZ)];
        sW1[r * P1 + c] = v;
    }
    for (int idx = tid; idx < OPC * H_SZ; idx += NTHR) {
        int r = idx >> 9, c = idx & 511;
        sWo[r * POW + c] = Wout[(o0 + r) * H_SZ + c];
    }
    if (tid < RPC) {
        sBi0[tid] = bin0[r0 + tid];
        float tc = fminf(fmaxf(tau0[r0 + tid], 0.1f), 10.f);
        sIT0[tid] = DT_C / tc;
        sBi1[tid] = bin1[r0 + tid];
        tc = fminf(fmaxf(tau1[r0 + tid], 0.1f), 10.f);
        sIT1[tid] = DT_C / tc;
    }
    if (tid < OPC) sBo[tid] = bout[o0 + tid];

    // Lane decode: A/B phases: bits[0:1]=rt, bit[2]=bt, bits[3:4]=ksl, bits[5:7]=warp
    const int rt   = tid & 3;
    const int bt   = (tid >> 2) & 1;
    const int ksl  = (tid >> 3) & 3;
    const int wrp  = tid >> 5;
    const int ksg  = wrp * 4 + ksl;          // 0..31
    const int rbase = rt * 4;
    const int bbase = bt * 4;
    // C phase: bit0=rt, bit1=bt, bits[2:7]=ksg (0..63)
    const int rtC = tid & 1, btC = (tid >> 1) & 1;
    const int ksgC = tid >> 2;
    const int kbC = wrp * 64 + ((tid >> 2) & 7) * 4;
    const int kbA = wrp * 96 + ksl * 4;
    const int kbB = wrp * 128 + ksl * 4;

    // finalize decode (tid<128): rb = b*16 + r
    const int fb = tid >> 4, fr = tid & 15;

    unsigned bar_target = 0;

    for (int t = 0; t < T_LEN; t++) {
        const int pw = (t & 1) ^ 1;

        // ===== wait for A data (x(t), h0old), start h1old staging =====
        CP_WAIT(0);
        __syncthreads();
        // h1old -> sB cols 512:1024 (g_h1[pr] final since bar2 of t-1)
        stage_h<PBB, 512>(uB, &g_h1[t & 1][0][0], b0, st_bb, st_c);
        CP_COMMIT();

        // ===== Phase A GEMM =====
        {
            float acc[4][4] = {};
            mm44<6, 16, P0, PAA>(sW0, rbase, sA, bbase, kbA, acc);
#pragma unroll
            for (int i = 0; i < 4; i++)
#pragma unroll
                for (int j = 0; j < 4; j++)
                    sRed[(64 * bt + 16 * j + 4 * rt + i) * 33 + ksg] = acc[i][j];
        }
        __syncthreads();
        if (tid < 128) {
            const float* p = &sRed[(fb * 16 + fr) * 33];
            float s0 = 0.f, s1 = 0.f, s2 = 0.f, s3 = 0.f;
#pragma unroll
            for (int kk = 0; kk < 32; kk += 4) {
                s0 += p[kk]; s1 += p[kk + 1]; s2 += p[kk + 2]; s3 += p[kk + 3];
            }
            float sum = (s0 + s1) + (s2 + s3) + sBi0[fr];
            float tgt = tanhf(sum);
            float hold = sA[fb * PAA + 256 + r0 + fr];
            g_h0[pw][b0 + fb][r0 + fr] = hold + (tgt - hold) * sIT0[fr];
        }
        bar_target += 32;
        pod_bar(cnt, bar_target);

        // ===== post-bar1: stage h0new -> sB[0:512]; prefetch next step's A data =====
        stage_h<PBB, 0>(uB, &g_h0[pw][0][0], b0, st_bb, st_c);
        CP_COMMIT();
        if (t + 1 < T_LEN) {
            cpa16(uA + (st_bb * PAA + st_c) * 4,
                  &x[((size_t)(b0 + st_bb) * T_LEN + (t + 1)) * IN_SZ + st_c]);
            cpa16(uA + (st_bb * PAA + st_c + 128) * 4,
                  &x[((size_t)(b0 + st_bb) * T_LEN + (t + 1)) * IN_SZ + st_c + 128]);
            stage_h<PAA, 256>(uA, &g_h0[pw][0][0], b0, st_bb, st_c);
        }
        CP_COMMIT();
        CP_WAIT(1);   // h1old + h0new complete; next-A still in flight
        __syncthreads();

        // ===== Phase B GEMM =====
        {
            float acc[4][4] = {};
            mm44<8, 16, P1, PBB>(sW1, rbase, sB, bbase, kbB, acc);
#pragma unroll
            for (int i = 0; i < 4; i++)
#pragma unroll
                for (int j = 0; j < 4; j++)
                    sRed[(64 * bt + 16 * j + 4 * rt + i) * 33 + ksg] = acc[i][j];
        }
        __syncthreads();
        if (tid < 128) {
            const float* p = &sRed[(fb * 16 + fr) * 33];
            float s0 = 0.f, s1 = 0.f, s2 = 0.f, s3 = 0.f;
#pragma unroll
            for (int kk = 0; kk < 32; kk += 4) {
                s0 += p[kk]; s1 += p[kk + 1]; s2 += p[kk + 2]; s3 += p[kk + 3];
            }
            float sum = (s0 + s1) + (s2 + s3) + sBi1[fr];
            float tgt = tanhf(sum);
            float hold = sB[fb * PBB + 512 + r0 + fr];
            g_h1[pw][b0 + fb][r0 + fr] = hold + (tgt - hold) * sIT1[fr];
        }
        bar_target += 32;
        pod_bar(cnt, bar_target);

        // ===== post-bar2: stage h1new -> sC =====
        stage_h<PCC, 0>(uC, &g_h1[pw][0][0], b0, st_bb, st_c);
        CP_COMMIT();
        CP_WAIT(0);   // sC ready (also drains next-A prefetch)
        __syncthreads();

        // ===== Phase C: output projection + residual =====
        {
            float acc[4][4] = {};
            mm44<2, 32, POW, PCC>(sWo, rtC * 4, sC, btC * 4, kbC, acc);
#pragma unroll
            for (int i = 0; i < 4; i++)
#pragma unroll
                for (int j = 0; j < 4; j++)
                    sRed[(32 * btC + 8 * j + 4 * rtC + i) * 65 + ksgC] = acc[i][j];
        }
        __syncthreads();
        if (tid < 64) {
            const int cb = tid >> 3, co = tid & 7;
            float res = __ldg(&x[((size_t)(b0 + cb) * T_LEN + t) * IN_SZ + o0 + co]);
            const float* p = &sRed[(cb * 8 + co) * 65];
            float s0 = 0.f, s1 = 0.f, s2 = 0.f, s3 = 0.f;
#pragma unroll
            for (int kk = 0; kk < 64; kk += 4) {
                s0 += p[kk]; s1 += p[kk + 1]; s2 += p[kk + 2]; s3 += p[kk + 3];
            }
            float sum = (s0 + s1) + (s2 + s3);
            out[((size_t)(b0 + cb) * T_LEN + t) * OUT_SZ + o0 + co] = sum + sBo[co] + res;
        }
        __syncthreads();  // protect sRed before next step's phase A stores
    }
}

extern "C" void kernel_launch(void* const* d_in, const int* in_sizes, int n_in,
                              void* d_out, int out_size) {
    const float* x     = (const float*)d_in[0];
    const float* Win0  = (const float*)d_in[1];
    const float* bin0  = (const float*)d_in[2];
    const float* Wrec0 = (const float*)d_in[3];
    const float* tau0  = (const float*)d_in[4];
    const float* Win1  = (const float*)d_in[5];
    const float* bin1  = (const float*)d_in[6];
    const float* Wrec1 = (const float*)d_in[7];
    const float* tau1  = (const float*)d_in[8];
    const float* Wout  = (const float*)d_in[9];
    const float* bout  = (const float*)d_in[10];
    float* outp        = (float*)d_out;

    cudaFuncSetAttribute(rnn_persistent,
                         cudaFuncAttributeMaxDynamicSharedMemorySize, SMEM_BYTES);

    init_state_kernel<<<128, 256>>>();
    rnn_persistent<<<NCTA, NTHR, SMEM_BYTES>>>(x, Win0, bin0, Wrec0, tau0,
                                               Win1, bin1, Wrec1, tau1,
                                               Wout, bout, outp);
}

// round 5
// speedup vs baseline: 1.3429x; 1.0761x over previous
#include <cuda_runtime.h>
#include <math.h>
#include <stdint.h>

#define T_LEN  2048
#define B_SZ   32
#define IN_SZ  256
#define H_SZ   512
#define OUT_SZ 256
#define DT_C   0.1f

#define RGROUPS 32
#define BGROUPS 4
#define NCTA    128
#define RPC     16
#define OPC     8
#define BPC     8
#define NTHR    256

// Pitches (floats), %4==0 and ==4 (mod 32)
#define P0  772
#define P1  1028
#define POW 516
#define PAA 772    // sA: 256 x | 512 h0old
#define PBB 1028   // sB: 512 h0new | 512 h1old (h1old doubles as phase-C input)

#define SMEM_FLOATS (RPC*P0 + RPC*P1 + OPC*POW + BPC*PAA + BPC*PBB + 4224 + 4160 + 72)
#define SMEM_BYTES  (SMEM_FLOATS * 4)

typedef unsigned long long ull;

__device__ float    g_h0[2][B_SZ][H_SZ];
__device__ float    g_h1[2][B_SZ][H_SZ];
__device__ unsigned g_cnt[BGROUPS * 32];

__global__ void init_state_kernel() {
    int i = blockIdx.x * blockDim.x + threadIdx.x;
    const int n = 2 * B_SZ * H_SZ;
    if (i < n) {
        ((float*)g_h0)[i] = 0.0f;
        ((float*)g_h1)[i] = 0.0f;
    }
    if (i < BGROUPS * 32) g_cnt[i] = 0u;
}

__device__ __forceinline__ void cpa16(uint32_t dst, const void* src) {
    asm volatile("cp.async.cg.shared.global [%0], [%1], 16;"
                 :: "r"(dst), "l"(src) : "memory");
}
#define CP_COMMIT() asm volatile("cp.async.commit_group;" ::: "memory")
#define CP_WAIT(n)  asm volatile("cp.async.wait_group %0;" :: "n"(n) : "memory")

template<int PIT, int COFF>
__device__ __forceinline__ void stage_h(uint32_t ubase, const float* __restrict__ g,
                                        int b0, int bb, int c) {
#pragma unroll
    for (int q = 0; q < 4; q++) {
        cpa16(ubase + (bb * PIT + COFF + c + q * 128) * 4,
              &g[(size_t)(b0 + bb) * H_SZ + c + q * 128]);
    }
}

__device__ __forceinline__ void pod_bar(unsigned* cnt, unsigned target) {
    __syncthreads();
    if (threadIdx.x == 0) {
        __threadfence();
        atomicAdd(cnt, 1u);
        unsigned v;
        do {
            asm volatile("ld.acquire.gpu.global.u32 %0, [%1];"
                         : "=r"(v) : "l"(cnt) : "memory");
        } while (v < target);
    }
    __syncthreads();
}

// packed dual-fp32 FMA (FFMA2) — PTX-only form
__device__ __forceinline__ void fmax2(ull& d, ull a, ull b) {
    asm("fma.rn.f32x2 %0, %1, %2, %0;" : "+l"(d) : "l"(a), "l"(b));
}
__device__ __forceinline__ float x2sum(ull v) {
    float lo, hi;
    asm("mov.b64 {%0,%1}, %2;" : "=f"(lo), "=f"(hi) : "l"(v));
    return lo + hi;
}

// 4x4 micro-tile, packed f32x2 along k. Each iter consumes 4 k-values.
template<int NIT, int KSTEP, int PW, int PAcc>
__device__ __forceinline__ void mm44p(const float* __restrict__ sW, int rbase,
                                      const float* __restrict__ sAct, int bbase,
                                      int kbase, ull acc[4][4]) {
#pragma unroll
    for (int it = 0; it < NIT; ++it) {
        const int k = kbase + it * KSTEP;
        ulonglong2 w[4], a[4];
#pragma unroll
        for (int i = 0; i < 4; i++)
            w[i] = *(const ulonglong2*)(sW + (rbase + i) * PW + k);
#pragma unroll
        for (int j = 0; j < 4; j++)
            a[j] = *(const ulonglong2*)(sAct + (bbase + j) * PAcc + k);
#pragma unroll
        for (int i = 0; i < 4; i++)
#pragma unroll
            for (int j = 0; j < 4; j++) {
                fmax2(acc[i][j], w[i].x, a[j].x);
                fmax2(acc[i][j], w[i].y, a[j].y);
            }
    }
}

__global__ void __launch_bounds__(NTHR, 1)
rnn_persistent(const float* __restrict__ x,
               const float* __restrict__ Win0, const float* __restrict__ bin0,
               const float* __restrict__ Wrec0, const float* __restrict__ tau0,
               const float* __restrict__ Win1, const float* __restrict__ bin1,
               const float* __restrict__ Wrec1, const float* __restrict__ tau1,
               const float* __restrict__ Wout, const float* __restrict__ bout,
               float* __restrict__ out)
{
    extern __shared__ float sm[];
    float* sW0   = sm;                   // [16][P0]
    float* sW1   = sW0 + RPC * P0;       // [16][P1]
    float* sWo   = sW1 + RPC * P1;       // [8][POW]
    float* sA    = sWo + OPC * POW;      // [8][PAA]
    float* sB    = sA  + BPC * PAA;      // [8][PBB]
    float* sRedA = sB  + BPC * PBB;      // 128*33 = 4224
    float* sRedC = sRedA + 4224;         // 64*65 = 4160
    float* sBi0  = sRedC + 4160;         // 16
    float* sIT0  = sBi0 + RPC;
    float* sBi1  = sIT0 + RPC;
    float* sIT1  = sBi1 + RPC;
    float* sBo   = sIT1 + RPC;           // 8

    const int tid = threadIdx.x;
    const int rg  = blockIdx.x & (RGROUPS - 1);
    const int bg  = blockIdx.x >> 5;
    const int b0  = bg * BPC;
    const int r0  = rg * RPC;
    const int o0  = rg * OPC;
    unsigned* cnt = &g_cnt[bg * 32];

    const uint32_t uA = (uint32_t)__cvta_generic_to_shared(sA);
    const uint32_t uB = (uint32_t)__cvta_generic_to_shared(sB);

    const int st_bb = tid >> 5;            // 0..7
    const int st_c  = (tid & 31) * 4;      // 0..124

    // ---- Prologue staging: x(0) and h0(-1)=0 -> sA ; h1(-1)=0 -> sB[512:] ----
    cpa16(uA + (st_bb * PAA + st_c) * 4,
          &x[((size_t)(b0 + st_bb) * T_LEN + 0) * IN_SZ + st_c]);
    cpa16(uA + (st_bb * PAA + st_c + 128) * 4,
          &x[((size_t)(b0 + st_bb) * T_LEN + 0) * IN_SZ + st_c + 128]);
    stage_h<PAA, 256>(uA, &g_h0[0][0][0], b0, st_bb, st_c);
    stage_h<PBB, 512>(uB, &g_h1[0][0][0], b0, st_bb, st_c);
    CP_COMMIT();

    // ---- Weights into SMEM (once) ----
    for (int idx = tid; idx < RPC * 768; idx += NTHR) {
        int r = idx / 768, c = idx % 768;
        float v = (c < IN_SZ) ? Win0[(r0 + r) * IN_SZ + c]
                              : Wrec0[(r0 + r) * H_SZ + (c - IN_SZ)];
        sW0[r * P0 + c] = v;
    }
    for (int idx = tid; idx < RPC * 1024; idx += NTHR) {
        int r = idx >> 10, c = idx & 1023;
        float v = (c < H_SZ) ? Win1[(r0 + r) * H_SZ + c]
                             : Wrec1[(r0 + r) * H_SZ + (c - H_SZ)];
        sW1[r * P1 + c] = v;
    }
    for (int idx = tid; idx < OPC * H_SZ; idx += NTHR) {
        int r = idx >> 9, c = idx & 511;
        sWo[r * POW + c] = Wout[(o0 + r) * H_SZ + c];
    }
    if (tid < RPC) {
        sBi0[tid] = bin0[r0 + tid];
        float tc = fminf(fmaxf(tau0[r0 + tid], 0.1f), 10.f);
        sIT0[tid] = DT_C / tc;
        sBi1[tid] = bin1[r0 + tid];
        tc = fminf(fmaxf(tau1[r0 + tid], 0.1f), 10.f);
        sIT1[tid] = DT_C / tc;
    }
    if (tid < OPC) sBo[tid] = bout[o0 + tid];

    // A/B decode: bits[0:1]=rt, bit2=bt, bits[3:4]=ksl, bits[5:7]=warp
    const int rt    = tid & 3;
    const int bt    = (tid >> 2) & 1;
    const int ksl   = (tid >> 3) & 3;
    const int wrp   = tid >> 5;
    const int ksg   = wrp * 4 + ksl;
    const int rbase = rt * 4;
    const int bbase = bt * 4;
    // C decode: bit0=rtC, bit1=btC, bits[2:7]=ksgC
    const int rtC = tid & 1, btC = (tid >> 1) & 1;
    const int ksgC = tid >> 2;
    const int kbC = wrp * 64 + ((tid >> 2) & 7) * 4;
    const int kbA = wrp * 96 + ksl * 4;
    const int kbB = wrp * 128 + ksl * 4;

    const int fb = tid >> 4, fr = tid & 15;      // A/B reduce (tid<128)
    const int cb = (tid - 128) >> 3, co = tid & 7;  // C reduce (tid in [128,192))

    unsigned bar_target = 0;

    for (int t = 0; t < T_LEN; t++) {
        const int pw = (t & 1) ^ 1;

        // ===== all staged data ready =====
        CP_WAIT(0);
        __syncthreads();

        // ===== Phase A(t) GEMM + Phase C(t-1) GEMM (fused region) =====
        {
            ull acc[4][4] = {};
            mm44p<6, 16, P0, PAA>(sW0, rbase, sA, bbase, kbA, acc);
#pragma unroll
            for (int i = 0; i < 4; i++)
#pragma unroll
                for (int j = 0; j < 4; j++)
                    sRedA[(64 * bt + 16 * j + 4 * rt + i) * 33 + ksg] = x2sum(acc[i][j]);
        }
        if (t) {
            ull acc[4][4] = {};
            mm44p<2, 32, POW, PBB>(sWo, rtC * 4, sB + 512, btC * 4, kbC, acc);
#pragma unroll
            for (int i = 0; i < 4; i++)
#pragma unroll
                for (int j = 0; j < 4; j++)
                    sRedC[(32 * btC + 8 * j + 4 * rtC + i) * 65 + ksgC] = x2sum(acc[i][j]);
        }
        __syncthreads();

        // ===== reductions: h0(t) on warps 0-3, out(t-1) on warps 4-5 =====
        if (tid < 128) {
            const float* p = &sRedA[(fb * 16 + fr) * 33];
            float s0 = 0.f, s1 = 0.f, s2 = 0.f, s3 = 0.f;
#pragma unroll
            for (int kk = 0; kk < 32; kk += 4) {
                s0 += p[kk]; s1 += p[kk + 1]; s2 += p[kk + 2]; s3 += p[kk + 3];
            }
            float sum = (s0 + s1) + (s2 + s3) + sBi0[fr];
            float tgt = tanhf(sum);
            float hold = sA[fb * PAA + 256 + r0 + fr];
            g_h0[pw][b0 + fb][r0 + fr] = hold + (tgt - hold) * sIT0[fr];
        } else if (t && tid < 192) {
            float res = __ldg(&x[((size_t)(b0 + cb) * T_LEN + (t - 1)) * IN_SZ + o0 + co]);
            const float* p = &sRedC[(cb * 8 + co) * 65];
            float s0 = 0.f, s1 = 0.f, s2 = 0.f, s3 = 0.f;
#pragma unroll
            for (int kk = 0; kk < 64; kk += 4) {
                s0 += p[kk]; s1 += p[kk + 1]; s2 += p[kk + 2]; s3 += p[kk + 3];
            }
            out[((size_t)(b0 + cb) * T_LEN + (t - 1)) * OUT_SZ + o0 + co]
                = (s0 + s1) + (s2 + s3) + sBo[co] + res;
        }
        bar_target += 32;
        pod_bar(cnt, bar_target);

        // ===== post-bar1: stage h0new -> sB[0:512] (G1); prefetch A(t+1) (G2) =====
        stage_h<PBB, 0>(uB, &g_h0[pw][0][0], b0, st_bb, st_c);
        CP_COMMIT();
        if (t + 1 < T_LEN) {
            cpa16(uA + (st_bb * PAA + st_c) * 4,
                  &x[((size_t)(b0 + st_bb) * T_LEN + (t + 1)) * IN_SZ + st_c]);
            cpa16(uA + (st_bb * PAA + st_c + 128) * 4,
                  &x[((size_t)(b0 + st_bb) * T_LEN + (t + 1)) * IN_SZ + st_c + 128]);
            stage_h<PAA, 256>(uA, &g_h0[pw][0][0], b0, st_bb, st_c);
        }
        CP_COMMIT();
        CP_WAIT(1);   // h0new landed; next-A may still fly
        __syncthreads();

        // ===== Phase B(t) GEMM =====
        {
            ull acc[4][4] = {};
            mm44p<8, 16, P1, PBB>(sW1, rbase, sB, bbase, kbB, acc);
#pragma unroll
            for (int i = 0; i < 4; i++)
#pragma unroll
                for (int j = 0; j < 4; j++)
                    sRedA[(64 * bt + 16 * j + 4 * rt + i) * 33 + ksg] = x2sum(acc[i][j]);
        }
        __syncthreads();
        if (tid < 128) {
            const float* p = &sRedA[(fb * 16 + fr) * 33];
            float s0 = 0.f, s1 = 0.f, s2 = 0.f, s3 = 0.f;
#pragma unroll
            for (int kk = 0; kk < 32; kk += 4) {
                s0 += p[kk]; s1 += p[kk + 1]; s2 += p[kk + 2]; s3 += p[kk + 3];
            }
            float sum = (s0 + s1) + (s2 + s3) + sBi1[fr];
            float tgt = tanhf(sum);
            float hold = sB[fb * PBB + 512 + r0 + fr];
            g_h1[pw][b0 + fb][r0 + fr] = hold + (tgt - hold) * sIT1[fr];
        }
        bar_target += 32;
        pod_bar(cnt, bar_target);

        // ===== post-bar2: stage h1(t) -> sB[512:] (G3; C(t) + B(t+1) input) =====
        stage_h<PBB, 512>(uB, &g_h1[pw][0][0], b0, st_bb, st_c);
        CP_COMMIT();
    }

    // ===== Epilogue: Phase C for t = T-1 =====
    CP_WAIT(0);
    __syncthreads();
    {
        ull acc[4][4] = {};
        mm44p<2, 32, POW, PBB>(sWo, rtC * 4, sB + 512, btC * 4, kbC, acc);
#pragma unroll
        for (int i = 0; i < 4; i++)
#pragma unroll
            for (int j = 0; j < 4; j++)
                sRedC[(32 * btC + 8 * j + 4 * rtC + i) * 65 + ksgC] = x2sum(acc[i][j]);
    }
    __syncthreads();
    if (tid < 64) {
        const int eb = tid >> 3, eo = tid & 7;
        float res = __ldg(&x[((size_t)(b0 + eb) * T_LEN + (T_LEN - 1)) * IN_SZ + o0 + eo]);
        const float* p = &sRedC[(eb * 8 + eo) * 65];
        float s0 = 0.f, s1 = 0.f, s2 = 0.f, s3 = 0.f;
#pragma unroll
        for (int kk = 0; kk < 64; kk += 4) {
            s0 += p[kk]; s1 += p[kk + 1]; s2 += p[kk + 2]; s3 += p[kk + 3];
        }
        out[((size_t)(b0 + eb) * T_LEN + (T_LEN - 1)) * OUT_SZ + o0 + eo]
            = (s0 + s1) + (s2 + s3) + sBo[eo] + res;
    }
}

extern "C" void kernel_launch(void* const* d_in, const int* in_sizes, int n_in,
                              void* d_out, int out_size) {
    const float* x     = (const float*)d_in[0];
    const float* Win0  = (const float*)d_in[1];
    const float* bin0  = (const float*)d_in[2];
    const float* Wrec0 = (const float*)d_in[3];
    const float* tau0  = (const float*)d_in[4];
    const float* Win1  = (const float*)d_in[5];
    const float* bin1  = (const float*)d_in[6];
    const float* Wrec1 = (const float*)d_in[7];
    const float* tau1  = (const float*)d_in[8];
    const float* Wout  = (const float*)d_in[9];
    const float* bout  = (const float*)d_in[10];
    float* outp        = (float*)d_out;

    cudaFuncSetAttribute(rnn_persistent,
                         cudaFuncAttributeMaxDynamicSharedMemorySize, SMEM_BYTES);

    init_state_kernel<<<128, 256>>>();
    rnn_persistent<<<NCTA, NTHR, SMEM_BYTES>>>(x, Win0, bin0, Wrec0, tau0,
                                               Win1, bin1, Wrec1, tau1,
                                               Wout, bout, outp);
}

// round 6
// speedup vs baseline: 1.7490x; 1.3024x over previous
#include <cuda_runtime.h>
#include <math.h>
#include <stdint.h>

#define T_LEN  2048
#define B_SZ   32
#define IN_SZ  256
#define H_SZ   512
#define OUT_SZ 256
#define DT_C   0.1f

#define RGROUPS 32
#define BGROUPS 4
#define NCTA    128
#define RPC     16
#define OPC     8
#define BPC     8
#define NTHR    256

// Pitches (floats), %4==0 and ==4 (mod 32)
#define P0  772
#define P1  1028
#define POW 516
#define PAX 260    // sA: x only (256 used)
#define PBB 1028   // sB: 512 h0 | 512 h1

#define SMEM_FLOATS (RPC*P0 + RPC*P1 + OPC*POW + BPC*PAX + BPC*PBB + 4224 + 4160 + 72)
#define SMEM_BYTES  (SMEM_FLOATS * 4)

typedef unsigned long long ull;

__device__ float    g_h0[2][B_SZ][H_SZ];
__device__ float    g_h1[2][B_SZ][H_SZ];
__device__ unsigned g_cnt[BGROUPS * 32];

__global__ void init_state_kernel() {
    int i = blockIdx.x * blockDim.x + threadIdx.x;
    const int n = 2 * B_SZ * H_SZ;
    if (i < n) {
        ((float*)g_h0)[i] = 0.0f;
        ((float*)g_h1)[i] = 0.0f;
    }
    if (i < BGROUPS * 32) g_cnt[i] = 0u;
}

__device__ __forceinline__ void cpa16(uint32_t dst, const void* src) {
    asm volatile("cp.async.cg.shared.global [%0], [%1], 16;"
                 :: "r"(dst), "l"(src) : "memory");
}
#define CP_COMMIT() asm volatile("cp.async.commit_group;" ::: "memory")
#define CP_WAIT(n)  asm volatile("cp.async.wait_group %0;" :: "n"(n) : "memory")

template<int PIT, int COFF>
__device__ __forceinline__ void stage_h(uint32_t ubase, const float* __restrict__ g,
                                        int b0, int bb, int c) {
#pragma unroll
    for (int q = 0; q < 4; q++) {
        cpa16(ubase + (bb * PIT + COFF + c + q * 128) * 4,
              &g[(size_t)(b0 + bb) * H_SZ + c + q * 128]);
    }
}

// split barrier: arrive (release) / spin (acquire). tid0 only, after __syncthreads.
__device__ __forceinline__ void bar_arrive(unsigned* cnt) {
    __threadfence();
    atomicAdd(cnt, 1u);
}
__device__ __forceinline__ void bar_spin(const unsigned* cnt, unsigned target) {
    unsigned v;
    do {
        asm volatile("ld.acquire.gpu.global.u32 %0, [%1];"
                     : "=r"(v) : "l"(cnt) : "memory");
    } while (v < target);
}

// packed dual-fp32 FMA (FFMA2)
__device__ __forceinline__ void fmax2(ull& d, ull a, ull b) {
    asm("fma.rn.f32x2 %0, %1, %2, %0;" : "+l"(d) : "l"(a), "l"(b));
}
__device__ __forceinline__ float x2sum(ull v) {
    float lo, hi;
    asm("mov.b64 {%0,%1}, %2;" : "=f"(lo), "=f"(hi) : "l"(v));
    return lo + hi;
}

// 4x4 micro-tile, packed f32x2, separate weight/activation column bases.
template<int NIT, int KSTEP, int PW, int PAcc>
__device__ __forceinline__ void mm44p2(const float* __restrict__ sW, int rbase, int wk,
                                       const float* __restrict__ sAct, int bbase, int ak,
                                       ull acc[4][4]) {
#pragma unroll
    for (int it = 0; it < NIT; ++it) {
        ulonglong2 w[4], a[4];
#pragma unroll
        for (int i = 0; i < 4; i++)
            w[i] = *(const ulonglong2*)(sW + (rbase + i) * PW + wk + it * KSTEP);
#pragma unroll
        for (int j = 0; j < 4; j++)
            a[j] = *(const ulonglong2*)(sAct + (bbase + j) * PAcc + ak + it * KSTEP);
#pragma unroll
        for (int i = 0; i < 4; i++)
#pragma unroll
            for (int j = 0; j < 4; j++) {
                fmax2(acc[i][j], w[i].x, a[j].x);
                fmax2(acc[i][j], w[i].y, a[j].y);
            }
    }
}

__global__ void __launch_bounds__(NTHR, 1)
rnn_persistent(const float* __restrict__ x,
               const float* __restrict__ Win0, const float* __restrict__ bin0,
               const float* __restrict__ Wrec0, const float* __restrict__ tau0,
               const float* __restrict__ Win1, const float* __restrict__ bin1,
               const float* __restrict__ Wrec1, const float* __restrict__ tau1,
               const float* __restrict__ Wout, const float* __restrict__ bout,
               float* __restrict__ out)
{
    extern __shared__ float sm[];
    float* sW0   = sm;                   // [16][P0]
    float* sW1   = sW0 + RPC * P0;       // [16][P1]
    float* sWo   = sW1 + RPC * P1;       // [8][POW]
    float* sA    = sWo + OPC * POW;      // [8][PAX]  x(t)
    float* sB    = sA  + BPC * PAX;      // [8][PBB]  h0 | h1
    float* sRedA = sB  + BPC * PBB;      // 128*33
    float* sRedC = sRedA + 4224;         // 64*65
    float* sBi0  = sRedC + 4160;
    float* sIT0  = sBi0 + RPC;
    float* sBi1  = sIT0 + RPC;
    float* sIT1  = sBi1 + RPC;
    float* sBo   = sIT1 + RPC;

    const int tid = threadIdx.x;
    const int rg  = blockIdx.x & (RGROUPS - 1);
    const int bg  = blockIdx.x >> 5;
    const int b0  = bg * BPC;
    const int r0  = rg * RPC;
    const int o0  = rg * OPC;
    unsigned* cnt = &g_cnt[bg * 32];

    const uint32_t uA = (uint32_t)__cvta_generic_to_shared(sA);
    const uint32_t uB = (uint32_t)__cvta_generic_to_shared(sB);

    const int st_bb = tid >> 5;            // 0..7
    const int st_c  = (tid & 31) * 4;      // 0..124

    // ---- Prologue staging: x(0)->sA, h0(-1)->sB[0:512], h1(-1)->sB[512:] ----
    cpa16(uA + (st_bb * PAX + st_c) * 4,
          &x[((size_t)(b0 + st_bb) * T_LEN + 0) * IN_SZ + st_c]);
    cpa16(uA + (st_bb * PAX + st_c + 128) * 4,
          &x[((size_t)(b0 + st_bb) * T_LEN + 0) * IN_SZ + st_c + 128]);
    stage_h<PBB, 0>(uB, &g_h0[0][0][0], b0, st_bb, st_c);
    stage_h<PBB, 512>(uB, &g_h1[0][0][0], b0, st_bb, st_c);
    CP_COMMIT();

    // ---- Weights into SMEM (once) ----
    for (int idx = tid; idx < RPC * 768; idx += NTHR) {
        int r = idx / 768, c = idx % 768;
        float v = (c < IN_SZ) ? Win0[(r0 + r) * IN_SZ + c]
                              : Wrec0[(r0 + r) * H_SZ + (c - IN_SZ)];
        sW0[r * P0 + c] = v;
    }
    for (int idx = tid; idx < RPC * 1024; idx += NTHR) {
        int r = idx >> 10, c = idx & 1023;
        float v = (c < H_SZ) ? Win1[(r0 + r) * H_SZ + c]
                             : Wrec1[(r0 + r) * H_SZ + (c - H_SZ)];
        sW1[r * P1 + c] = v;
    }
    for (int idx = tid; idx < OPC * H_SZ; idx += NTHR) {
        int r = idx >> 9, c = idx & 511;
        sWo[r * POW + c] = Wout[(o0 + r) * H_SZ + c];
    }
    if (tid < RPC) {
        sBi0[tid] = bin0[r0 + tid];
        float tc = fminf(fmaxf(tau0[r0 + tid], 0.1f), 10.f);
        sIT0[tid] = DT_C / tc;
        sBi1[tid] = bin1[r0 + tid];
        tc = fminf(fmaxf(tau1[r0 + tid], 0.1f), 10.f);
        sIT1[tid] = DT_C / tc;
    }
    if (tid < OPC) sBo[tid] = bout[o0 + tid];

    // A/B decode
    const int rt    = tid & 3;
    const int bt    = (tid >> 2) & 1;
    const int ksl   = (tid >> 3) & 3;
    const int wrp   = tid >> 5;
    const int ksg   = wrp * 4 + ksl;
    const int rbase = rt * 4;
    const int bbase = bt * 4;
    const int kx = wrp * 32 + ksl * 4;   // A x-part  (covers 256)
    const int kh = wrp * 64 + ksl * 4;   // h-halves  (covers 512)
    // C decode
    const int rtC = tid & 1, btC = (tid >> 1) & 1;
    const int ksgC = tid >> 2;
    const int kbC = wrp * 64 + ((tid >> 2) & 7) * 4;

    const int fb = tid >> 4, fr = tid & 15;         // A/B reduce (tid<128)
    const int cb = (tid - 128) >> 3, co = tid & 7;  // C reduce (tid in [128,192))

    // ---- Prologue compute: A(0) GEMM ----
    CP_WAIT(0);
    __syncthreads();
    {
        ull acc[4][4] = {};
        mm44p2<2, 16, P0, PAX>(sW0, rbase, kx, sA, bbase, kx, acc);
        mm44p2<4, 16, P0, PBB>(sW0, rbase, 256 + kh, sB, bbase, kh, acc);
#pragma unroll
        for (int i = 0; i < 4; i++)
#pragma unroll
            for (int j = 0; j < 4; j++)
                sRedA[(64 * bt + 16 * j + 4 * rt + i) * 33 + ksg] = x2sum(acc[i][j]);
    }

    unsigned barc = 0;

    for (int t = 0; t < T_LEN; t++) {
        const int pw = (t & 1) ^ 1;

        // (1) ensure h1(t-1) fetch landed; sRedA(A(t)) stores visible
        CP_WAIT(0);
        __syncthreads();

        // (2) A-reduce -> h0(t)
        if (tid < 128) {
            const float* p = &sRedA[(fb * 16 + fr) * 33];
            float s0 = 0.f, s1 = 0.f, s2 = 0.f, s3 = 0.f;
#pragma unroll
            for (int kk = 0; kk < 32; kk += 4) {
                s0 += p[kk]; s1 += p[kk + 1]; s2 += p[kk + 2]; s3 += p[kk + 3];
            }
            float sum = (s0 + s1) + (s2 + s3) + sBi0[fr];
            float tgt = tanhf(sum);
            float hold = sB[fb * PBB + r0 + fr];     // h0(t-1)
            g_h0[pw][b0 + fb][r0 + fr] = hold + (tgt - hold) * sIT0[fr];
        }
        __syncthreads();
        barc += 32;
        if (tid == 0) bar_arrive(cnt);               // bar1 arrive

        // (3) B1 GEMM (h1(t-1) half) — hides peer arrival skew
        ull accB[4][4] = {};
        mm44p2<4, 16, P1, PBB>(sW1, rbase, 512 + kh, sB, bbase, 512 + kh, accB);

        if (tid == 0) bar_spin(cnt, barc);           // bar1 spin
        __syncthreads();

        // (4) fetch h0(t) -> sB[0:512] (group 1); x(t+1) -> sA (group 2)
        stage_h<PBB, 0>(uB, &g_h0[pw][0][0], b0, st_bb, st_c);
        CP_COMMIT();
        if (t + 1 < T_LEN) {
            cpa16(uA + (st_bb * PAX + st_c) * 4,
                  &x[((size_t)(b0 + st_bb) * T_LEN + (t + 1)) * IN_SZ + st_c]);
            cpa16(uA + (st_bb * PAX + st_c + 128) * 4,
                  &x[((size_t)(b0 + st_bb) * T_LEN + (t + 1)) * IN_SZ + st_c + 128]);
        }
        CP_COMMIT();

        // (5) C(t-1) GEMM — hides h0 fetch latency
        if (t) {
            ull accC[4][4] = {};
            mm44p2<2, 32, POW, PBB>(sWo, rtC * 4, kbC, sB, btC * 4, 512 + kbC, accC);
#pragma unroll
            for (int i = 0; i < 4; i++)
#pragma unroll
                for (int j = 0; j < 4; j++)
                    sRedC[(32 * btC + 8 * j + 4 * rtC + i) * 65 + ksgC] = x2sum(accC[i][j]);
        }

        CP_WAIT(1);   // h0 group done (x group may still fly)
        __syncthreads();

        // (6) B2 GEMM (h0(t) half), same accumulators
        mm44p2<4, 16, P1, PBB>(sW1, rbase, kh, sB, bbase, kh, accB);
#pragma unroll
        for (int i = 0; i < 4; i++)
#pragma unroll
            for (int j = 0; j < 4; j++)
                sRedA[(64 * bt + 16 * j + 4 * rt + i) * 33 + ksg] = x2sum(accB[i][j]);
        __syncthreads();

        // (7) B-reduce -> h1(t) on warps 0-3; C-reduce -> out(t-1) on warps 4-5
        if (tid < 128) {
            const float* p = &sRedA[(fb * 16 + fr) * 33];
            float s0 = 0.f, s1 = 0.f, s2 = 0.f, s3 = 0.f;
#pragma unroll
            for (int kk = 0; kk < 32; kk += 4) {
                s0 += p[kk]; s1 += p[kk + 1]; s2 += p[kk + 2]; s3 += p[kk + 3];
            }
            float sum = (s0 + s1) + (s2 + s3) + sBi1[fr];
            float tgt = tanhf(sum);
            float hold = sB[fb * PBB + 512 + r0 + fr];  // h1(t-1)
            g_h1[pw][b0 + fb][r0 + fr] = hold + (tgt - hold) * sIT1[fr];
        } else if (t && tid < 192) {
            float res = __ldg(&x[((size_t)(b0 + cb) * T_LEN + (t - 1)) * IN_SZ + o0 + co]);
            const float* p = &sRedC[(cb * 8 + co) * 65];
            float s0 = 0.f, s1 = 0.f, s2 = 0.f, s3 = 0.f;
#pragma unroll
            for (int kk = 0; kk < 64; kk += 4) {
                s0 += p[kk]; s1 += p[kk + 1]; s2 += p[kk + 2]; s3 += p[kk + 3];
            }
            out[((size_t)(b0 + cb) * T_LEN + (t - 1)) * OUT_SZ + o0 + co]
                = (s0 + s1) + (s2 + s3) + sBo[co] + res;
        }
        __syncthreads();
        barc += 32;
        if (tid == 0) bar_arrive(cnt);               // bar2 arrive

        // (8) A(t+1) GEMM — hides bar2 skew + h1 fetch
        if (t + 1 < T_LEN) {
            CP_WAIT(0);                              // x(t+1) landed
            ull accA[4][4] = {};
            mm44p2<2, 16, P0, PAX>(sW0, rbase, kx, sA, bbase, kx, accA);
            mm44p2<4, 16, P0, PBB>(sW0, rbase, 256 + kh, sB, bbase, kh, accA);
#pragma unroll
            for (int i = 0; i < 4; i++)
#pragma unroll
                for (int j = 0; j < 4; j++)
                    sRedA[(64 * bt + 16 * j + 4 * rt + i) * 33 + ksg] = x2sum(accA[i][j]);
        }

        if (tid == 0) bar_spin(cnt, barc);           // bar2 spin
        __syncthreads();

        // (9) fetch h1(t) -> sB[512:]
        stage_h<PBB, 512>(uB, &g_h1[pw][0][0], b0, st_bb, st_c);
        CP_COMMIT();
    }

    // ===== Epilogue: out(T-1) =====
    CP_WAIT(0);
    __syncthreads();
    {
        ull accC[4][4] = {};
        mm44p2<2, 32, POW, PBB>(sWo, rtC * 4, kbC, sB, btC * 4, 512 + kbC, accC);
#pragma unroll
        for (int i = 0; i < 4; i++)
#pragma unroll
            for (int j = 0; j < 4; j++)
                sRedC[(32 * btC + 8 * j + 4 * rtC + i) * 65 + ksgC] = x2sum(accC[i][j]);
    }
    __syncthreads();
    if (tid < 64) {
        const int eb = tid >> 3, eo = tid & 7;
        float res = __ldg(&x[((size_t)(b0 + eb) * T_LEN + (T_LEN - 1)) * IN_SZ + o0 + eo]);
        const float* p = &sRedC[(eb * 8 + eo) * 65];
        float s0 = 0.f, s1 = 0.f, s2 = 0.f, s3 = 0.f;
#pragma unroll
        for (int kk = 0; kk < 64; kk += 4) {
            s0 += p[kk]; s1 += p[kk + 1]; s2 += p[kk + 2]; s3 += p[kk + 3];
        }
        out[((size_t)(b0 + eb) * T_LEN + (T_LEN - 1)) * OUT_SZ + o0 + eo]
            = (s0 + s1) + (s2 + s3) + sBo[eo] + res;
    }
}

extern "C" void kernel_launch(void* const* d_in, const int* in_sizes, int n_in,
                              void* d_out, int out_size) {
    const float* x     = (const float*)d_in[0];
    const float* Win0  = (const float*)d_in[1];
    const float* bin0  = (const float*)d_in[2];
    const float* Wrec0 = (const float*)d_in[3];
    const float* tau0  = (const float*)d_in[4];
    const float* Win1  = (const float*)d_in[5];
    const float* bin1  = (const float*)d_in[6];
    const float* Wrec1 = (const float*)d_in[7];
    const float* tau1  = (const float*)d_in[8];
    const float* Wout  = (const float*)d_in[9];
    const float* bout  = (const float*)d_in[10];
    float* outp        = (float*)d_out;

    cudaFuncSetAttribute(rnn_persistent,
                         cudaFuncAttributeMaxDynamicSharedMemorySize, SMEM_BYTES);

    init_state_kernel<<<128, 256>>>();
    rnn_persistent<<<NCTA, NTHR, SMEM_BYTES>>>(x, Win0, bin0, Wrec0, tau0,
                                               Win1, bin1, Wrec1, tau1,
                                               Wout, bout, outp);
}